// round 6
// baseline (speedup 1.0000x reference)
#include <cuda_runtime.h>
#include <stdint.h>

#define FULL 0xFFFFFFFFu

constexpr int N_ITEMS = 32;
constexpr int WARPS_PER_BLOCK = 8;
constexpr int ROWS_TOTAL = 262144;
constexpr int NBLOCKS = ROWS_TOTAL / WARPS_PER_BLOCK;   // 32768

// Scratch for deterministic two-pass reduction (no cudaMalloc allowed).
__device__ float g_psum[NBLOCKS];
__device__ int   g_pcnt[NBLOCKS];
__device__ unsigned g_done;   // zero-initialized; last block resets it each run
// Dtype-detection flags: g_rank64 != 0 -> ranks are int64; g_mask32 != 0 -> mask is int32.
__device__ int g_rank64;
__device__ int g_mask32;

// Detect dtypes by sampling 64 positions. ranks values are in [0,32):
//  - int64: uint32 view has high word (odd index) == 0 everywhere.
//  - int32: odd-index words are uniform [0,32); 64 samples all-zero ~ (1/32)^64 = never.
// mask 0/1: int32 -> bytes at 4i+1 always 0; bool -> random 0/1 there.
__global__ void detect_kernel(const uint32_t* __restrict__ ranks_u32,
                              const uint8_t*  __restrict__ mask_u8)
{
    const int lane = threadIdx.x;  // 32 threads
    uint32_t acc_r = ranks_u32[2 * lane + 1] | ranks_u32[2 * (lane + 32) + 1];
    uint32_t acc_m = mask_u8[4 * lane + 1]  | mask_u8[4 * (lane + 32) + 1];
    #pragma unroll
    for (int off = 16; off; off >>= 1) {
        acc_r |= __shfl_xor_sync(FULL, acc_r, off);
        acc_m |= __shfl_xor_sync(FULL, acc_m, off);
    }
    if (lane == 0) {
        g_rank64 = (acc_r == 0) ? 1 : 0;
        g_mask32 = (acc_m == 0) ? 1 : 0;
    }
}

__global__ __launch_bounds__(WARPS_PER_BLOCK * 32)
void pl_rows_kernel(const float* __restrict__ scores,
                    const void*  __restrict__ ranks_raw,
                    const void*  __restrict__ mask_raw,
                    float* __restrict__ out)
{
    __shared__ float sh_bin[WARPS_PER_BLOCK][32];
    __shared__ float sh_e[WARPS_PER_BLOCK][32];
    __shared__ float sh_T[WARPS_PER_BLOCK][32];
    __shared__ float sh_psum[WARPS_PER_BLOCK];
    __shared__ int   sh_pcnt[WARPS_PER_BLOCK];
    __shared__ int   sh_last;

    const int warp = threadIdx.x >> 5;
    const int lane = threadIdx.x & 31;
    const int row  = blockIdx.x * WARPS_PER_BLOCK + warp;
    const int idx  = row * N_ITEMS + lane;

    const int rank64 = g_rank64;
    const int mask32 = g_mask32;

    // Coalesced loads per warp.
    const float s = scores[idx];
    int r;
    if (rank64) r = (int)((const long long*)ranks_raw)[idx];
    else        r = ((const int*)ranks_raw)[idx];
    bool valid;
    if (mask32) valid = (((const int*)mask_raw)[idx] == 0);
    else        valid = (((const uint8_t*)mask_raw)[idx] == 0);

    const unsigned vm = __ballot_sync(FULL, valid);
    const int n = __popc(vm);

    // exp(s): scores ~ N(0,1) -> no overflow risk, skip the max pass.
    const float e = valid ? __expf(s) : 0.0f;
    sh_e[warp][lane]   = e;
    sh_bin[warp][lane] = 0.0f;
    __syncwarp();
    if (valid) atomicAdd(&sh_bin[warp][r], e);   // per-rank bin totals
    __syncwarp();

    // Inclusive suffix sum over the 32 rank bins: T[v] = sum_{w>=v} B[w]
    float T = sh_bin[warp][lane];
    #pragma unroll
    for (int off = 1; off < 32; off <<= 1) {
        float t = __shfl_down_sync(FULL, T, off);
        if (lane + off < 32) T += t;
    }
    sh_T[warp][lane] = T;
    __syncwarp();

    // Same-rank lower-lane correction: W = sum of e over peers with lower lane.
    // Give invalid lanes unique keys so they never group with valid ones.
    const int mkey = valid ? r : (64 + lane);
    unsigned peers = __match_any_sync(FULL, mkey);
    unsigned low   = peers & ((1u << lane) - 1u);
    float W = 0.0f;
    while (low) {
        int l = __ffs(low) - 1;
        low &= low - 1;
        W += sh_e[warp][l];
    }
    // inclusive suffix of e over sorted order (rank, lane) for this item
    const float sufx = valid ? (sh_T[warp][r] - W) : 1.0f;

    // Last item in sorted order = max key (r<<5 | lane) among valid lanes.
    int key = valid ? ((r << 5) | lane) : -1;
    int mk = key;
    #pragma unroll
    for (int off = 16; off; off >>= 1)
        mk = max(mk, __shfl_xor_sync(FULL, mk, off));
    const bool islast = valid && (key == mk);

    float contrib = (valid && !islast) ? (s - __logf(sufx)) : 0.0f;
    #pragma unroll
    for (int off = 16; off; off >>= 1)
        contrib += __shfl_xor_sync(FULL, contrib, off);

    const float per_row = (n >= 2) ? (-contrib / (float)n) : 0.0f;

    if (lane == 0) { sh_psum[warp] = per_row; sh_pcnt[warp] = (n >= 2); }
    __syncthreads();

    if (threadIdx.x == 0) {
        float bs = 0.0f; int bc = 0;
        #pragma unroll
        for (int w = 0; w < WARPS_PER_BLOCK; w++) { bs += sh_psum[w]; bc += sh_pcnt[w]; }
        g_psum[blockIdx.x] = bs;
        g_pcnt[blockIdx.x] = bc;
        __threadfence();
        unsigned t = atomicAdd(&g_done, 1u);
        sh_last = (t == (unsigned)(gridDim.x - 1));
    }
    __syncthreads();

    // Last block performs the final deterministic reduction.
    if (sh_last) {
        float acc = 0.0f; int cnt = 0;
        for (int i = threadIdx.x; i < NBLOCKS; i += WARPS_PER_BLOCK * 32) {
            acc += g_psum[i];
            cnt += g_pcnt[i];
        }
        // warp reduce
        #pragma unroll
        for (int off = 16; off; off >>= 1) {
            acc += __shfl_xor_sync(FULL, acc, off);
            cnt += __shfl_xor_sync(FULL, cnt, off);
        }
        if (lane == 0) { sh_psum[warp] = acc; sh_pcnt[warp] = cnt; }
        __syncthreads();
        if (threadIdx.x == 0) {
            float fs = 0.0f; int fc = 0;
            #pragma unroll
            for (int w = 0; w < WARPS_PER_BLOCK; w++) { fs += sh_psum[w]; fc += sh_pcnt[w]; }
            out[0] = fs / (float)(fc > 0 ? fc : 1);
            g_done = 0;   // reset for next graph replay
        }
    }
}

extern "C" void kernel_launch(void* const* d_in, const int* in_sizes, int n_in,
                              void* d_out, int out_size)
{
    const float* scores = (const float*)d_in[0];
    const void*  ranks  = d_in[1];
    const void*  mask   = d_in[2];
    float* out = (float*)d_out;

    detect_kernel<<<1, 32>>>((const uint32_t*)ranks, (const uint8_t*)mask);
    pl_rows_kernel<<<NBLOCKS, WARPS_PER_BLOCK * 32>>>(scores, ranks, mask, out);
}

// round 9
// speedup vs baseline: 1.7584x; 1.7584x over previous
#include <cuda_runtime.h>
#include <stdint.h>

#define FULL 0xFFFFFFFFu

constexpr int N_ITEMS = 32;
constexpr int WARPS_PER_BLOCK = 8;
constexpr int ROWS_TOTAL = 262144;
constexpr int NBLOCKS = ROWS_TOTAL / WARPS_PER_BLOCK;   // 32768

// Scratch for deterministic two-pass reduction (no cudaMalloc allowed).
__device__ float g_psum[NBLOCKS];
__device__ int   g_pcnt[NBLOCKS];
// Dtype-detection flags: g_rank64 != 0 -> ranks are int64; g_mask32 != 0 -> mask is int32.
__device__ int g_rank64;
__device__ int g_mask32;

// Detect dtypes by sampling 64 positions. ranks values are in [0,32):
//  - int64: uint32 view has high word (odd index) == 0 everywhere.
//  - int32: odd-index words are uniform [0,32); 64 samples all-zero ~ (1/32)^64 = never.
// mask 0/1: int32 -> bytes at 4i+1 always 0; bool -> random 0/1 there.
__global__ void detect_kernel(const uint32_t* __restrict__ ranks_u32,
                              const uint8_t*  __restrict__ mask_u8)
{
    const int lane = threadIdx.x;  // 32 threads
    uint32_t acc_r = ranks_u32[2 * lane + 1] | ranks_u32[2 * (lane + 32) + 1];
    uint32_t acc_m = mask_u8[4 * lane + 1]  | mask_u8[4 * (lane + 32) + 1];
    #pragma unroll
    for (int off = 16; off; off >>= 1) {
        acc_r |= __shfl_xor_sync(FULL, acc_r, off);
        acc_m |= __shfl_xor_sync(FULL, acc_m, off);
    }
    if (lane == 0) {
        g_rank64 = (acc_r == 0) ? 1 : 0;
        g_mask32 = (acc_m == 0) ? 1 : 0;
    }
}

__global__ __launch_bounds__(WARPS_PER_BLOCK * 32)
void pl_rows_kernel(const float* __restrict__ scores,
                    const void*  __restrict__ ranks_raw,
                    const void*  __restrict__ mask_raw)
{
    __shared__ float sh_sort[WARPS_PER_BLOCK][32];
    __shared__ float sh_psum[WARPS_PER_BLOCK];
    __shared__ int   sh_pcnt[WARPS_PER_BLOCK];

    const int warp = threadIdx.x >> 5;
    const int lane = threadIdx.x & 31;
    const int row  = blockIdx.x * WARPS_PER_BLOCK + warp;
    const int idx  = row * N_ITEMS + lane;

    const int rank64 = g_rank64;
    const int mask32 = g_mask32;

    // Coalesced loads per warp.
    const float s = scores[idx];
    int r;
    if (rank64) r = (int)((const long long*)ranks_raw)[idx];
    else        r = ((const int*)ranks_raw)[idx];
    bool valid;
    if (mask32) valid = (((const int*)mask_raw)[idx] == 0);
    else        valid = (((const uint8_t*)mask_raw)[idx] == 0);

    const unsigned vm = __ballot_sync(FULL, valid);
    const int n = __popc(vm);

    // ---- stable sorted position via 5-bit radix rank (ballots, no shared/atomics) ----
    // p = #{valid j: r_j < r} + #{valid j: r_j == r, lane_j < lane}
    int count = 0;
    unsigned M = vm;                 // candidates sharing our high bits so far (valid only)
    #pragma unroll
    for (int b = 4; b >= 0; --b) {
        const unsigned B = __ballot_sync(FULL, (r >> b) & 1);
        if ((r >> b) & 1) { count += __popc(M & ~B); M &= B; }
        else              { M &= ~B; }
    }
    const int p = count + __popc(M & ((1u << lane) - 1u));  // stable tie-break

    if (valid) sh_sort[warp][p] = s;
    __syncwarp();
    const float sv = sh_sort[warp][lane];          // garbage for lane >= n (guarded below)

    // exp on sorted value; scores ~ N(0,1) so no overflow: skip max-subtraction.
    const float es = (lane < n) ? __expf(sv) : 0.0f;

    // inclusive reverse (suffix) sum over positions
    float suf = es;
    #pragma unroll
    for (int off = 1; off < 32; off <<= 1) {
        const float t = __shfl_down_sync(FULL, suf, off);
        if (lane + off < 32) suf += t;
    }

    // term_k = s_k - log(suffix_k) for k < n-1
    float term = (lane < n - 1) ? (sv - __logf(suf)) : 0.0f;
    #pragma unroll
    for (int off = 16; off; off >>= 1)
        term += __shfl_xor_sync(FULL, term, off);

    const float per_row = (n >= 2) ? (-term / (float)n) : 0.0f;

    if (lane == 0) { sh_psum[warp] = per_row; sh_pcnt[warp] = (n >= 2); }
    __syncthreads();

    if (threadIdx.x == 0) {
        float bs = 0.0f; int bc = 0;
        #pragma unroll
        for (int w = 0; w < WARPS_PER_BLOCK; w++) { bs += sh_psum[w]; bc += sh_pcnt[w]; }
        g_psum[blockIdx.x] = bs;
        g_pcnt[blockIdx.x] = bc;
    }
}

__global__ __launch_bounds__(256)
void pl_final_kernel(float* __restrict__ out)
{
    __shared__ float ssum[256];
    __shared__ int   scnt[256];

    float acc = 0.0f; int cnt = 0;
    for (int i = threadIdx.x; i < NBLOCKS; i += 256) {
        acc += g_psum[i];
        cnt += g_pcnt[i];
    }
    ssum[threadIdx.x] = acc;
    scnt[threadIdx.x] = cnt;
    __syncthreads();

    #pragma unroll
    for (int s = 128; s; s >>= 1) {
        if (threadIdx.x < s) {
            ssum[threadIdx.x] += ssum[threadIdx.x + s];
            scnt[threadIdx.x] += scnt[threadIdx.x + s];
        }
        __syncthreads();
    }
    if (threadIdx.x == 0) {
        int c = scnt[0];
        out[0] = ssum[0] / (float)(c > 0 ? c : 1);
    }
}

extern "C" void kernel_launch(void* const* d_in, const int* in_sizes, int n_in,
                              void* d_out, int out_size)
{
    const float* scores = (const float*)d_in[0];
    const void*  ranks  = d_in[1];
    const void*  mask   = d_in[2];
    float* out = (float*)d_out;

    detect_kernel<<<1, 32>>>((const uint32_t*)ranks, (const uint8_t*)mask);
    pl_rows_kernel<<<NBLOCKS, WARPS_PER_BLOCK * 32>>>(scores, ranks, mask);
    pl_final_kernel<<<1, 256>>>(out);
}

// round 11
// speedup vs baseline: 2.2529x; 1.2813x over previous
#include <cuda_runtime.h>
#include <stdint.h>

#define FULL 0xFFFFFFFFu

constexpr int N_ITEMS = 32;
constexpr int WARPS_PER_BLOCK = 8;
constexpr int ROWS_PER_WARP = 2;
constexpr int ROWS_PER_BLOCK = WARPS_PER_BLOCK * ROWS_PER_WARP;   // 16
constexpr int ROWS_TOTAL = 262144;
constexpr int NBLOCKS = ROWS_TOTAL / ROWS_PER_BLOCK;              // 16384

// Scratch for deterministic two-pass reduction (no cudaMalloc allowed).
__device__ float g_psum[NBLOCKS];
__device__ int   g_pcnt[NBLOCKS];

__global__ __launch_bounds__(WARPS_PER_BLOCK * 32)
void pl_rows_kernel(const float* __restrict__ scores,
                    const void*  __restrict__ ranks_raw,
                    const void*  __restrict__ mask_raw)
{
    __shared__ float sh_sort[WARPS_PER_BLOCK][ROWS_PER_WARP][N_ITEMS];
    __shared__ float sh_psum[ROWS_PER_BLOCK];
    __shared__ int   sh_pcnt[ROWS_PER_BLOCK];
    __shared__ int   sh_flags[2];   // [0]: rank high-word nonzero seen, [1]: mask byte4i+1 nonzero seen

    const int tid  = threadIdx.x;
    const int warp = tid >> 5;
    const int lane = tid & 31;

    // ---- inline dtype detection, sampling items [0,256) (same addresses for
    // every block -> L2 broadcast). ranks in [0,32):
    //  int64 -> uint32 word 2i+1 always 0;  int32 -> uniform [0,32), 256 samples
    //  all-zero ~ (1/32)^256 = never.  mask 0/1: int32 -> byte 4i+1 always 0;
    //  bool -> random 0/1 there, 2^-256 = never.  In-bounds under either dtype.
    const uint32_t hiw = ((const uint32_t*)ranks_raw)[2 * tid + 1];
    const uint32_t mbt = ((const uint8_t*)mask_raw)[4 * tid + 1];
    if (tid < 2) sh_flags[tid] = 0;
    __syncthreads();
    if (hiw) sh_flags[0] = 1;        // benign race: same value written
    if (mbt) sh_flags[1] = 1;
    __syncthreads();
    const bool rank64 = (sh_flags[0] == 0);
    const bool mask32 = (sh_flags[1] == 0);

    const int row0 = blockIdx.x * ROWS_PER_BLOCK + warp * ROWS_PER_WARP;

    // ---- two independent rows per warp: all chains interleave (ILP=2) ----
    float s[ROWS_PER_WARP]; int r[ROWS_PER_WARP]; bool valid[ROWS_PER_WARP];
    #pragma unroll
    for (int q = 0; q < ROWS_PER_WARP; q++) {
        const int idx = (row0 + q) * N_ITEMS + lane;
        s[q] = scores[idx];
        r[q] = rank64 ? (int)((const long long*)ranks_raw)[idx]
                      : ((const int*)ranks_raw)[idx];
        valid[q] = mask32 ? (((const int*)mask_raw)[idx] == 0)
                          : (((const uint8_t*)mask_raw)[idx] == 0);
    }

    unsigned vm[ROWS_PER_WARP]; int n[ROWS_PER_WARP];
    #pragma unroll
    for (int q = 0; q < ROWS_PER_WARP; q++) {
        vm[q] = __ballot_sync(FULL, valid[q]);
        n[q]  = __popc(vm[q]);
    }

    // stable sorted position via 5-bit radix rank (vote pipe, no shared/atomics):
    // p = #{valid j: r_j < r} + #{valid j: r_j == r, lane_j < lane}
    int count[ROWS_PER_WARP] = {};
    unsigned M[ROWS_PER_WARP];
    #pragma unroll
    for (int q = 0; q < ROWS_PER_WARP; q++) M[q] = vm[q];
    #pragma unroll
    for (int b = 4; b >= 0; --b) {
        #pragma unroll
        for (int q = 0; q < ROWS_PER_WARP; q++) {
            const unsigned B = __ballot_sync(FULL, (r[q] >> b) & 1);
            if ((r[q] >> b) & 1) { count[q] += __popc(M[q] & ~B); M[q] &= B; }
            else                 { M[q] &= ~B; }
        }
    }
    int p[ROWS_PER_WARP];
    #pragma unroll
    for (int q = 0; q < ROWS_PER_WARP; q++)
        p[q] = count[q] + __popc(M[q] & ((1u << lane) - 1u));

    #pragma unroll
    for (int q = 0; q < ROWS_PER_WARP; q++)
        if (valid[q]) sh_sort[warp][q][p[q]] = s[q];
    __syncwarp();

    float sv[ROWS_PER_WARP], es[ROWS_PER_WARP];
    #pragma unroll
    for (int q = 0; q < ROWS_PER_WARP; q++) {
        sv[q] = sh_sort[warp][q][lane];                 // garbage for lane >= n (guarded)
        es[q] = (lane < n[q]) ? __expf(sv[q]) : 0.0f;   // N(0,1) scores: no overflow, skip max pass
    }

    // inclusive reverse (suffix) sum over sorted positions
    float suf[ROWS_PER_WARP];
    #pragma unroll
    for (int q = 0; q < ROWS_PER_WARP; q++) suf[q] = es[q];
    #pragma unroll
    for (int off = 1; off < 32; off <<= 1) {
        #pragma unroll
        for (int q = 0; q < ROWS_PER_WARP; q++) {
            const float t = __shfl_down_sync(FULL, suf[q], off);
            if (lane + off < 32) suf[q] += t;
        }
    }

    // term_k = s_k - log(suffix_k) for k < n-1, then warp-reduce
    float term[ROWS_PER_WARP];
    #pragma unroll
    for (int q = 0; q < ROWS_PER_WARP; q++)
        term[q] = (lane < n[q] - 1) ? (sv[q] - __logf(suf[q])) : 0.0f;
    #pragma unroll
    for (int off = 16; off; off >>= 1) {
        #pragma unroll
        for (int q = 0; q < ROWS_PER_WARP; q++)
            term[q] += __shfl_xor_sync(FULL, term[q], off);
    }

    if (lane == 0) {
        #pragma unroll
        for (int q = 0; q < ROWS_PER_WARP; q++) {
            const int rr = warp * ROWS_PER_WARP + q;
            sh_psum[rr] = (n[q] >= 2) ? (-term[q] / (float)n[q]) : 0.0f;
            sh_pcnt[rr] = (n[q] >= 2);
        }
    }
    __syncthreads();

    if (tid == 0) {
        float bs = 0.0f; int bc = 0;
        #pragma unroll
        for (int w = 0; w < ROWS_PER_BLOCK; w++) { bs += sh_psum[w]; bc += sh_pcnt[w]; }
        g_psum[blockIdx.x] = bs;
        g_pcnt[blockIdx.x] = bc;
    }
}

__global__ __launch_bounds__(256)
void pl_final_kernel(float* __restrict__ out)
{
    __shared__ float ssum[256];
    __shared__ int   scnt[256];

    float acc = 0.0f; int cnt = 0;
    for (int i = threadIdx.x; i < NBLOCKS; i += 256) {
        acc += g_psum[i];
        cnt += g_pcnt[i];
    }
    ssum[threadIdx.x] = acc;
    scnt[threadIdx.x] = cnt;
    __syncthreads();

    #pragma unroll
    for (int s = 128; s; s >>= 1) {
        if (threadIdx.x < s) {
            ssum[threadIdx.x] += ssum[threadIdx.x + s];
            scnt[threadIdx.x] += scnt[threadIdx.x + s];
        }
        __syncthreads();
    }
    if (threadIdx.x == 0) {
        int c = scnt[0];
        out[0] = ssum[0] / (float)(c > 0 ? c : 1);
    }
}

extern "C" void kernel_launch(void* const* d_in, const int* in_sizes, int n_in,
                              void* d_out, int out_size)
{
    const float* scores = (const float*)d_in[0];
    const void*  ranks  = d_in[1];
    const void*  mask   = d_in[2];
    float* out = (float*)d_out;

    pl_rows_kernel<<<NBLOCKS, WARPS_PER_BLOCK * 32>>>(scores, ranks, mask);
    pl_final_kernel<<<1, 256>>>(out);
}

// round 12
// speedup vs baseline: 2.6352x; 1.1697x over previous
#include <cuda_runtime.h>
#include <stdint.h>

#define FULL 0xFFFFFFFFu

constexpr int N_ITEMS = 32;
constexpr int WARPS_PER_BLOCK = 8;
constexpr int ROWS_PER_WARP = 4;
constexpr int ROWS_PER_BLOCK = WARPS_PER_BLOCK * ROWS_PER_WARP;   // 32
constexpr int ROWS_TOTAL = 262144;
constexpr int NBLOCKS = ROWS_TOTAL / ROWS_PER_BLOCK;              // 8192

// Packed per-block partials: (sum, count-as-float). Counts <= 2^24 are exact in fp32.
__device__ float2 g_part[NBLOCKS];

__global__ __launch_bounds__(WARPS_PER_BLOCK * 32)
void pl_rows_kernel(const float* __restrict__ scores,
                    const void*  __restrict__ ranks_raw,
                    const void*  __restrict__ mask_raw)
{
    __shared__ float sh_sort[WARPS_PER_BLOCK][ROWS_PER_WARP][N_ITEMS];
    __shared__ float sh_psum[ROWS_PER_BLOCK];
    __shared__ int   sh_pcnt[ROWS_PER_BLOCK];
    __shared__ int   sh_flags[2];   // [0]: rank high-word nonzero seen, [1]: mask byte4i+1 nonzero seen

    const int tid  = threadIdx.x;
    const int warp = tid >> 5;
    const int lane = tid & 31;

    // ---- inline dtype detection, sampling items [0,256) (same addresses for
    // every block -> L2 broadcast). ranks in [0,32):
    //  int64 -> uint32 word 2i+1 always 0;  int32 -> uniform [0,32), 256 samples
    //  all-zero ~ (1/32)^256 = never.  mask 0/1: int32 -> byte 4i+1 always 0;
    //  bool -> random 0/1 there, 2^-256 = never.  In-bounds under either dtype.
    const uint32_t hiw = ((const uint32_t*)ranks_raw)[2 * tid + 1];
    const uint32_t mbt = ((const uint8_t*)mask_raw)[4 * tid + 1];
    if (tid < 2) sh_flags[tid] = 0;
    __syncthreads();
    if (hiw) sh_flags[0] = 1;        // benign race: same value written
    if (mbt) sh_flags[1] = 1;
    __syncthreads();
    const bool rank64 = (sh_flags[0] == 0);
    const bool mask32 = (sh_flags[1] == 0);

    const int row0 = blockIdx.x * ROWS_PER_BLOCK + warp * ROWS_PER_WARP;

    // ---- four independent rows per warp: all chains interleave (ILP=4) ----
    float s[ROWS_PER_WARP]; int r[ROWS_PER_WARP]; bool valid[ROWS_PER_WARP];
    #pragma unroll
    for (int q = 0; q < ROWS_PER_WARP; q++) {
        const int idx = (row0 + q) * N_ITEMS + lane;
        s[q] = scores[idx];
        r[q] = rank64 ? (int)((const long long*)ranks_raw)[idx]
                      : ((const int*)ranks_raw)[idx];
        valid[q] = mask32 ? (((const int*)mask_raw)[idx] == 0)
                          : (((const uint8_t*)mask_raw)[idx] == 0);
    }

    unsigned vm[ROWS_PER_WARP]; int n[ROWS_PER_WARP];
    #pragma unroll
    for (int q = 0; q < ROWS_PER_WARP; q++) {
        vm[q] = __ballot_sync(FULL, valid[q]);
        n[q]  = __popc(vm[q]);
    }

    // stable sorted position via 5-bit radix rank (vote pipe, no shared/atomics):
    // p = #{valid j: r_j < r} + #{valid j: r_j == r, lane_j < lane}
    int count[ROWS_PER_WARP] = {};
    unsigned M[ROWS_PER_WARP];
    #pragma unroll
    for (int q = 0; q < ROWS_PER_WARP; q++) M[q] = vm[q];
    #pragma unroll
    for (int b = 4; b >= 0; --b) {
        #pragma unroll
        for (int q = 0; q < ROWS_PER_WARP; q++) {
            const unsigned B = __ballot_sync(FULL, (r[q] >> b) & 1);
            if ((r[q] >> b) & 1) { count[q] += __popc(M[q] & ~B); M[q] &= B; }
            else                 { M[q] &= ~B; }
        }
    }
    int p[ROWS_PER_WARP];
    #pragma unroll
    for (int q = 0; q < ROWS_PER_WARP; q++)
        p[q] = count[q] + __popc(M[q] & ((1u << lane) - 1u));

    #pragma unroll
    for (int q = 0; q < ROWS_PER_WARP; q++)
        if (valid[q]) sh_sort[warp][q][p[q]] = s[q];
    __syncwarp();

    float sv[ROWS_PER_WARP], es[ROWS_PER_WARP];
    #pragma unroll
    for (int q = 0; q < ROWS_PER_WARP; q++) {
        sv[q] = sh_sort[warp][q][lane];                 // garbage for lane >= n (guarded)
        es[q] = (lane < n[q]) ? __expf(sv[q]) : 0.0f;   // N(0,1) scores: no overflow, skip max pass
    }

    // inclusive reverse (suffix) sum over sorted positions
    float suf[ROWS_PER_WARP];
    #pragma unroll
    for (int q = 0; q < ROWS_PER_WARP; q++) suf[q] = es[q];
    #pragma unroll
    for (int off = 1; off < 32; off <<= 1) {
        #pragma unroll
        for (int q = 0; q < ROWS_PER_WARP; q++) {
            const float t = __shfl_down_sync(FULL, suf[q], off);
            if (lane + off < 32) suf[q] += t;
        }
    }

    // term_k = s_k - log(suffix_k) for k < n-1, then warp-reduce
    float term[ROWS_PER_WARP];
    #pragma unroll
    for (int q = 0; q < ROWS_PER_WARP; q++)
        term[q] = (lane < n[q] - 1) ? (sv[q] - __logf(suf[q])) : 0.0f;
    #pragma unroll
    for (int off = 16; off; off >>= 1) {
        #pragma unroll
        for (int q = 0; q < ROWS_PER_WARP; q++)
            term[q] += __shfl_xor_sync(FULL, term[q], off);
    }

    if (lane == 0) {
        #pragma unroll
        for (int q = 0; q < ROWS_PER_WARP; q++) {
            const int rr = warp * ROWS_PER_WARP + q;
            sh_psum[rr] = (n[q] >= 2) ? (-term[q] / (float)n[q]) : 0.0f;
            sh_pcnt[rr] = (n[q] >= 2);
        }
    }
    __syncthreads();

    if (tid == 0) {
        float bs = 0.0f; int bc = 0;
        #pragma unroll
        for (int w = 0; w < ROWS_PER_BLOCK; w++) { bs += sh_psum[w]; bc += sh_pcnt[w]; }
        g_part[blockIdx.x] = make_float2(bs, (float)bc);
    }
}

// Final reduction: 1024 threads, vectorized float4 loads over 8192 float2 partials
// (64 KB, L2-resident). Each thread handles 4 float4 = 8 float2 entries.
__global__ __launch_bounds__(1024)
void pl_final_kernel(float* __restrict__ out)
{
    __shared__ float2 sh_acc[32];

    const int tid  = threadIdx.x;
    const int warp = tid >> 5;
    const int lane = tid & 31;

    const float4* pv = (const float4*)g_part;      // NBLOCKS/2 = 4096 float4
    float acc = 0.0f, cnt = 0.0f;
    #pragma unroll
    for (int j = 0; j < NBLOCKS / 2 / 1024; j++) { // 4 iterations
        const float4 v = pv[tid + j * 1024];
        acc += v.x + v.z;
        cnt += v.y + v.w;
    }
    #pragma unroll
    for (int off = 16; off; off >>= 1) {
        acc += __shfl_xor_sync(FULL, acc, off);
        cnt += __shfl_xor_sync(FULL, cnt, off);
    }
    if (lane == 0) sh_acc[warp] = make_float2(acc, cnt);
    __syncthreads();

    if (warp == 0) {
        float2 v = sh_acc[lane];
        #pragma unroll
        for (int off = 16; off; off >>= 1) {
            v.x += __shfl_xor_sync(FULL, v.x, off);
            v.y += __shfl_xor_sync(FULL, v.y, off);
        }
        if (lane == 0)
            out[0] = v.x / fmaxf(v.y, 1.0f);
    }
}

extern "C" void kernel_launch(void* const* d_in, const int* in_sizes, int n_in,
                              void* d_out, int out_size)
{
    const float* scores = (const float*)d_in[0];
    const void*  ranks  = d_in[1];
    const void*  mask   = d_in[2];
    float* out = (float*)d_out;

    pl_rows_kernel<<<NBLOCKS, WARPS_PER_BLOCK * 32>>>(scores, ranks, mask);
    pl_final_kernel<<<1, 1024>>>(out);
}